// round 10
// baseline (speedup 1.0000x reference)
#include <cuda_runtime.h>
#include <cuda_bf16.h>

// Problem constants (S=8192, G=1024, T=4096, E=16384)
#define E_N 16384
#define T_N 4096
#define G_N 1024
#define CHUNK 32
#define NCHUNKS 128
#define NS 4                    // superchunks of 32 chunks
#define NBLK 128
#define NTHR 1024
#define G4 (G_N / 4)            // 256 group-quads
#define MWORDS 32               // 1024 groups / 32 bits

// Row-granular diff image [T][G]; read/zeroed sparsely via occupancy mask.
__device__ float g_rowdiff[T_N * G_N];
__device__ unsigned g_mask[T_N * MWORDS];        // 512 KB occupancy bits
// Chunk- and superchunk-level diffs, [group][chunk] contiguous rows.
// DOUBLE-BUFFERED on barrier parity: launch scatters into [p], zeroes [1-p]
// (whose readers all finished last launch -> no second barrier needed).
__device__ float g_cdiff[2][G_N * NCHUNKS];
__device__ float g_sdiff[2][G_N * NS];

// Grid barrier state (monotonic generation counter -> graph-replay-safe).
__device__ unsigned g_bar_arrive;
__device__ volatile unsigned g_bar_gen;

// One gpu-scope fence per CTA per side (scope promotion through bar.sync).
__device__ __forceinline__ void grid_barrier() {
    __syncthreads();
    if (threadIdx.x == 0) {
        __threadfence();
        unsigned gen = g_bar_gen;
        if (atomicAdd(&g_bar_arrive, 1) == NBLK - 1) {
            g_bar_arrive = 0;
            __threadfence();
            g_bar_gen = gen + 1;           // release
        } else {
            while (g_bar_gen == gen) { }   // poll (L2)
        }
        __threadfence();
    }
    __syncthreads();
}

__device__ __forceinline__ float4 ldcg4(const float4* p) { return __ldcg(p); }
__device__ __forceinline__ void stcg4(float4* p, float4 v) { __stcg(p, v); }

// ---------------------------------------------------------------------------
// One persistent kernel, ONE grid barrier.
// ---------------------------------------------------------------------------
__global__ void __launch_bounds__(NTHR, 1)
fused_kernel(const int*   __restrict__ index,
             const float* __restrict__ rate,
             const float* __restrict__ start,
             const float* __restrict__ endt,
             const float* __restrict__ t0,
             const int*   __restrict__ group_id,
             const float* __restrict__ weights,
             float*       __restrict__ out) {
    __shared__ float    s_t0[T_N];               // 16 KB; reused after barrier
    __shared__ unsigned s_mask[CHUNK * MWORDS];  // 4 KB chunk mask slice
    const int tid = threadIdx.x;
    const int blk = blockIdx.x;

    const unsigned p = g_bar_gen & 1u;     // stable: read before the barrier

    // ---------------- Phase A: event preprocess + diff scatter -------------
    ((float4*)s_t0)[tid] = ((const float4*)t0)[tid];

    const bool ev_active = tid < 128;
    const int e = blk * 128 + tid;
    float st = 0.f, en = 0.f, rt = 0.f, wsc = 0.f;
    int g = 0;
    if (ev_active) {
        st = __ldg(&start[e]);
        en = __ldg(&endt[e]);
        int src = __ldg(&index[e]);
        rt  = __ldg(&rate[e]);
        wsc = __ldg(&weights[src]);
        g   = __ldg(&group_id[src]);
    }

    // Zero the OTHER parity's cdiff/sdiff slice (used+read last launch).
    stcg4((float4*)g_cdiff[1 - p] + blk * (G_N * NCHUNKS / 4 / NBLK) + tid,
          make_float4(0.f, 0.f, 0.f, 0.f));
    if (tid < G_N * NS / 4 / NBLK)         // 8 float4 per block
        stcg4((float4*)g_sdiff[1 - p] + blk * (G_N * NS / 4 / NBLK) + tid,
              make_float4(0.f, 0.f, 0.f, 0.f));
    __syncthreads();

    if (ev_active) {
        // Branchless dual lower_bound over sorted t0 (4096 = 2^12).
        int a = 0, b = 0;
        #pragma unroll
        for (int s = T_N >> 1; s; s >>= 1) {
            a += (s_t0[a + s - 1] < st) ? s : 0;
            b += (s_t0[b + s - 1] < en) ? s : 0;
        }
        a += (s_t0[a] < st) ? 1 : 0;        // ts
        b += (s_t0[b] < en) ? 1 : 0;        // te

        const int ts = a, te = b;
        if (te > ts) {
            const float w = rt * wsc;
            // Row-level residues + occupancy bits.
            const unsigned bit = 1u << (g & 31);
            if (ts & (CHUNK - 1)) {
                atomicAdd(&g_rowdiff[ts * G_N + g],  w);
                atomicOr (&g_mask[ts * MWORDS + (g >> 5)], bit);
            }
            if ((te & (CHUNK - 1)) && te < T_N) {
                atomicAdd(&g_rowdiff[te * G_N + g], -w);
                atomicOr (&g_mask[te * MWORDS + (g >> 5)], bit);
            }
            // Chunk range [c0, c1) -> superchunk diff + chunk residues.
            const int c0 = (ts + CHUNK - 1) >> 5;
            const int c1 = (te + CHUNK - 1) >> 5;
            if (c0 != c1) {
                const int s0 = (c0 + 31) >> 5;   // ceil(c/32)
                const int s1 = (c1 + 31) >> 5;
                if (s0 != s1) {
                    if (s0 < NS) atomicAdd(&g_sdiff[p][g * NS + s0],  w);
                    if (s1 < NS) atomicAdd(&g_sdiff[p][g * NS + s1], -w);
                }
                if ((c0 & 31) && c0 < NCHUNKS)
                    atomicAdd(&g_cdiff[p][g * NCHUNKS + c0],  w);
                if ((c1 & 31) && c1 < NCHUNKS)
                    atomicAdd(&g_cdiff[p][g * NCHUNKS + c1], -w);
            }
        }
    }

    grid_barrier();   // the ONLY grid-wide sync

    // ---------------- Mask slice + sparse rowdiff prefetch -----------------
    const int qid = tid & (G4 - 1);        // group-quad 0..255
    const int rb  = tid >> 8;              // row-group 0..3
    const int tbeg = blk * CHUNK;

    s_mask[tid] = __ldcg(&g_mask[tbeg * MWORDS + tid]);

    // ---------------- Per-block carry (replaces phase B + barrier 2) -------
    // Thread tid computes carry for group g=tid into smem (reusing s_t0):
    // carry = sum_{s<=sb} sdiff[g][s] + sum_{c=32sb..blk} cdiff[g][c].
    const int sb = blk >> 5;
    float carry;
    {
        float4 s4 = ldcg4((const float4*)g_sdiff[p] + tid);   // g*NS/4 = tid
        carry = s4.x;                       // s=0 always included (sb>=0)
        if (sb >= 1) carry += s4.y;
        if (sb >= 2) carry += s4.z;
        if (sb >= 3) carry += s4.w;
        const float4* crow = (const float4*)g_cdiff[p] + tid * (NCHUNKS / 4);
        #pragma unroll
        for (int j = 0; j < 8; j++) {       // chunks 32sb+4j .. +3
            float4 c4 = ldcg4(crow + sb * 8 + j);
            const int cb = sb * 32 + j * 4;
            if (cb + 0 <= blk) carry += c4.x;
            if (cb + 1 <= blk) carry += c4.y;
            if (cb + 2 <= blk) carry += c4.z;
            if (cb + 3 <= blk) carry += c4.w;
        }
    }
    __syncthreads();                        // s_mask ready; s_t0 reusable
    s_t0[tid] = carry;                      // s_carry[g]

    // Sparse rowdiff prefetch (nibble of the quad's mask word).
    const int wix = qid >> 3;
    const int nsh = (qid & 7) * 4;
    float4 v[8];
    unsigned nz[8];
    #pragma unroll
    for (int i = 0; i < 8; i++) {
        nz[i] = (s_mask[(rb * 8 + i) * MWORDS + wix] >> nsh) & 0xFu;
        v[i] = nz[i] ? ldcg4((const float4*)g_rowdiff +
                             (size_t)(tbeg + rb * 8 + i) * G4 + qid)
                     : make_float4(0.f, 0.f, 0.f, 0.f);
    }

    // Local inclusive scan of the 8 rows.
    float4 run = make_float4(0.f, 0.f, 0.f, 0.f);
    float4 s[8];
    #pragma unroll
    for (int i = 0; i < 8; i++) {
        run.x += v[i].x; run.y += v[i].y; run.z += v[i].z; run.w += v[i].w;
        s[i] = run;
    }
    ((float4*)(s_t0 + G_N))[rb * G4 + qid] = run;  // row-group totals
    __syncthreads();

    // ---------------- Emit + sparse cleanup --------------------------------
    {
        float4 base = ((const float4*)s_t0)[qid];  // carry quad
        #pragma unroll
        for (int r = 0; r < 3; r++) {
            if (r < rb) {
                float4 t = ((const float4*)(s_t0 + G_N))[r * G4 + qid];
                base.x += t.x; base.y += t.y; base.z += t.z; base.w += t.w;
            }
        }
        float4* out4 = (float4*)out;
        float4* rdw4 = (float4*)g_rowdiff;
        const float4 z = make_float4(0.f, 0.f, 0.f, 0.f);
        #pragma unroll
        for (int i = 0; i < 8; i++) {
            float4 o;
            o.x = base.x + s[i].x;
            o.y = base.y + s[i].y;
            o.z = base.z + s[i].z;
            o.w = base.w + s[i].w;
            const size_t idx = (size_t)(tbeg + rb * 8 + i) * G4 + qid;
            stcg4(out4 + idx, o);
            if (nz[i]) stcg4(rdw4 + idx, z);        // sparse replay-clean
        }
        __stcg(&g_mask[tbeg * MWORDS + tid], 0u);   // mask replay-clean
    }
}

// ---------------------------------------------------------------------------
extern "C" void kernel_launch(void* const* d_in, const int* in_sizes, int n_in,
                              void* d_out, int out_size) {
    const int*   index    = (const int*)  d_in[0];
    const float* rate     = (const float*)d_in[1];
    const float* start    = (const float*)d_in[2];
    const float* endt     = (const float*)d_in[3];
    const float* t0       = (const float*)d_in[4];
    const int*   group_id = (const int*)  d_in[5];
    const float* weights  = (const float*)d_in[6];
    float* out = (float*)d_out;

    fused_kernel<<<NBLK, NTHR>>>(index, rate, start, endt, t0,
                                 group_id, weights, out);
}

// round 12
// speedup vs baseline: 1.0250x; 1.0250x over previous
#include <cuda_runtime.h>
#include <cuda_bf16.h>

// Problem constants (S=8192, G=1024, T=4096, E=16384)
#define E_N 16384
#define T_N 4096
#define G_N 1024
#define CHUNK 16
#define NCHUNKS 256             // T / CHUNK
#define NBLK 256
#define NTHR 1024
#define G4 (G_N / 4)            // 256 group-quads
#define MWORDS 32               // 1024 groups / 32 bits
#define EPB (E_N / NBLK)        // 64 events per block
#define SBUF (G_N + 4 * G_N)    // 5120 floats: carry + row-group totals
                                // (>= T_N, so also holds t0 for the search)

// Row-granular diff image [T][G]; read/zeroed sparsely via occupancy mask.
__device__ float g_rowdiff[T_N * G_N];
__device__ unsigned g_mask[T_N * MWORDS];        // 512 KB occupancy bits
// Chunk-granular diff, TRANSPOSED [group][chunk] (contiguous phase-B rows).
__device__ float g_cdiff[G_N * NCHUNKS];         // zeroed behind phase-B read
// Carry at each chunk start, [chunk][group] (fully rewritten each launch).
__device__ float g_carry[NCHUNKS * G_N];

// Grid barrier state (monotonic generation counter -> graph-replay-safe).
__device__ unsigned g_bar_arrive;
__device__ volatile unsigned g_bar_gen;

// One gpu-scope fence per CTA per side (scope promotion through bar.sync).
__device__ __forceinline__ void grid_barrier() {
    __syncthreads();
    if (threadIdx.x == 0) {
        __threadfence();
        unsigned gen = g_bar_gen;
        if (atomicAdd(&g_bar_arrive, 1) == NBLK - 1) {
            g_bar_arrive = 0;
            __threadfence();
            g_bar_gen = gen + 1;           // release
        } else {
            while (g_bar_gen == gen) { }   // poll (L2)
        }
        __threadfence();
    }
    __syncthreads();
}

__device__ __forceinline__ float4 ldcg4(const float4* p) { return __ldcg(p); }
__device__ __forceinline__ void stcg4(float4* p, float4 v) { __stcg(p, v); }

// ---------------------------------------------------------------------------
// Persistent kernel: 256 blocks x 1024 threads, 2 CTAs/SM (64 warps/SM).
// __launch_bounds__(1024, 2) caps regs at 32 -> occupancy 2 guaranteed, so
// the 256-block single-wave spin barrier cannot deadlock (2*148=296 slots).
// Shared layout (s_buf, 20 KB): phase A = t0[0..4095];
// post-barrier = carry[0..1023] ++ row-group totals[1024..5119].
// ---------------------------------------------------------------------------
__global__ void __launch_bounds__(NTHR, 2)
fused_kernel(const int*   __restrict__ index,
             const float* __restrict__ rate,
             const float* __restrict__ start,
             const float* __restrict__ endt,
             const float* __restrict__ t0,
             const int*   __restrict__ group_id,
             const float* __restrict__ weights,
             float*       __restrict__ out) {
    __shared__ float    s_buf[SBUF];             // 20 KB
    __shared__ unsigned s_mask[CHUNK * MWORDS];  // 2 KB
    const int tid = threadIdx.x;
    const int blk = blockIdx.x;

    // ---------------- Phase A: event preprocess + diff scatter -------------
    ((float4*)s_buf)[tid] = ((const float4*)t0)[tid];  // t0 -> s_buf[0..4095]

    const bool ev_active = tid < EPB;
    const int e = blk * EPB + tid;
    float st = 0.f, en = 0.f, rt = 0.f, wsc = 0.f;
    int g = 0;
    if (ev_active) {                        // hoisted, overlap with preload
        st = __ldg(&start[e]);
        en = __ldg(&endt[e]);
        int src = __ldg(&index[e]);
        rt  = __ldg(&rate[e]);
        wsc = __ldg(&weights[src]);
        g   = __ldg(&group_id[src]);
    }
    __syncthreads();

    if (ev_active) {
        // Branchless dual lower_bound over sorted t0 (4096 = 2^12).
        int a = 0, b = 0;
        #pragma unroll
        for (int s = T_N >> 1; s; s >>= 1) {
            a += (s_buf[a + s - 1] < st) ? s : 0;
            b += (s_buf[b + s - 1] < en) ? s : 0;
        }
        a += (s_buf[a] < st) ? 1 : 0;       // ts
        b += (s_buf[b] < en) ? 1 : 0;       // te

        const int ts = a, te = b;
        if (te > ts) {
            const float w = rt * wsc;
            // Row-level residues + occupancy bits (fire-and-forget REDs).
            const unsigned bit = 1u << (g & 31);
            if (ts & (CHUNK - 1)) {
                atomicAdd(&g_rowdiff[ts * G_N + g],  w);
                atomicOr (&g_mask[ts * MWORDS + (g >> 5)], bit);
            }
            if ((te & (CHUNK - 1)) && te < T_N) {
                atomicAdd(&g_rowdiff[te * G_N + g], -w);
                atomicOr (&g_mask[te * MWORDS + (g >> 5)], bit);
            }
            // Chunk-level diff (chunk = 16 rows).
            const int c0 = (ts + CHUNK - 1) >> 4;
            const int c1 = (te + CHUNK - 1) >> 4;
            if (c0 != c1) {
                if (c0 < NCHUNKS) atomicAdd(&g_cdiff[g * NCHUNKS + c0],  w);
                if (c1 < NCHUNKS) atomicAdd(&g_cdiff[g * NCHUNKS + c1], -w);
            }
        }
    }

    grid_barrier();   // barrier 1: all scatters globally visible

    const int qid = tid & (G4 - 1);        // group-quad 0..255
    const int rb  = tid >> 8;              // row-group 0..3 (4 rows each)
    const int tbeg = blk * CHUNK;

    // Chunk mask slice into smem (512 words).
    if (tid < CHUNK * MWORDS)
        s_mask[tid] = __ldcg(&g_mask[tbeg * MWORDS + tid]);

    // ---------------- Phase B: chunk-level prefix -> carry -----------------
    // Warp per group (4 groups per block): lane owns 8 consecutive chunks.
    {
        const int wid = tid >> 5, lid = tid & 31;
        if (wid < 4) {
            const int grp = blk * 4 + wid;
            float4* row = (float4*)g_cdiff + grp * (NCHUNKS / 4);
            float4 ca = ldcg4(row + lid * 2);
            float4 cb = ldcg4(row + lid * 2 + 1);
            float p1 = ca.x,      p2 = p1 + ca.y, p3 = p2 + ca.z, p4 = p3 + ca.w;
            float p5 = p4 + cb.x, p6 = p5 + cb.y, p7 = p6 + cb.z, p8 = p7 + cb.w;
            float sum = p8;                 // warp inclusive scan of lane sums
            #pragma unroll
            for (int o = 1; o < 32; o <<= 1) {
                float n = __shfl_up_sync(0xffffffffu, sum, o);
                if (lid >= o) sum += n;
            }
            const float off = sum - p8;     // exclusive prefix
            const int c = lid * 8;
            __stcg(&g_carry[(c + 0) * G_N + grp], off + p1);
            __stcg(&g_carry[(c + 1) * G_N + grp], off + p2);
            __stcg(&g_carry[(c + 2) * G_N + grp], off + p3);
            __stcg(&g_carry[(c + 3) * G_N + grp], off + p4);
            __stcg(&g_carry[(c + 4) * G_N + grp], off + p5);
            __stcg(&g_carry[(c + 5) * G_N + grp], off + p6);
            __stcg(&g_carry[(c + 6) * G_N + grp], off + p7);
            __stcg(&g_carry[(c + 7) * G_N + grp], off + p8);
            const float4 z = make_float4(0.f, 0.f, 0.f, 0.f);
            stcg4(row + lid * 2,     z);    // replay-clean
            stcg4(row + lid * 2 + 1, z);
        }
    }
    __syncthreads();   // s_mask ready; s_buf reusable

    // Sparse rowdiff load (nibble of the quad's mask word) + local scan.
    const int wix = qid >> 3;
    const int nsh = (qid & 7) * 4;
    float4 v[4];
    unsigned nz[4];
    #pragma unroll
    for (int i = 0; i < 4; i++) {
        nz[i] = (s_mask[(rb * 4 + i) * MWORDS + wix] >> nsh) & 0xFu;
        v[i] = nz[i] ? ldcg4((const float4*)g_rowdiff +
                             (size_t)(tbeg + rb * 4 + i) * G4 + qid)
                     : make_float4(0.f, 0.f, 0.f, 0.f);
    }
    float4 run = make_float4(0.f, 0.f, 0.f, 0.f);
    #pragma unroll
    for (int i = 0; i < 4; i++) {           // in-place inclusive scan
        run.x += v[i].x; run.y += v[i].y; run.z += v[i].z; run.w += v[i].w;
        v[i] = run;
    }
    // Row-group totals: s_buf floats [1024 .. 5119] (in-bounds: SBUF=5120).
    ((float4*)(s_buf + G_N))[rb * G4 + qid] = run;

    grid_barrier();   // barrier 2: carry globally visible

    // Coalesced carry load for this chunk -> s_buf[0..1023].
    s_buf[tid < G_N ? tid : 0] = tid < G_N
        ? __ldcg(&g_carry[blk * G_N + tid]) : s_buf[0];
    __syncthreads();

    // ---------------- Emit + sparse cleanup --------------------------------
    {
        float4 base = ((const float4*)s_buf)[qid];  // carry quad
        #pragma unroll
        for (int r = 0; r < 3; r++) {               // cross row-group prefix
            if (r < rb) {
                float4 t = ((const float4*)(s_buf + G_N))[r * G4 + qid];
                base.x += t.x; base.y += t.y; base.z += t.z; base.w += t.w;
            }
        }
        float4* out4 = (float4*)out;
        float4* rdw4 = (float4*)g_rowdiff;
        const float4 z = make_float4(0.f, 0.f, 0.f, 0.f);
        #pragma unroll
        for (int i = 0; i < 4; i++) {
            float4 o;
            o.x = base.x + v[i].x;
            o.y = base.y + v[i].y;
            o.z = base.z + v[i].z;
            o.w = base.w + v[i].w;
            const size_t idx = (size_t)(tbeg + rb * 4 + i) * G4 + qid;
            stcg4(out4 + idx, o);
            if (nz[i]) stcg4(rdw4 + idx, z);        // sparse replay-clean
        }
        if (tid < CHUNK * MWORDS)
            __stcg(&g_mask[tbeg * MWORDS + tid], 0u);  // mask replay-clean
    }
}

// ---------------------------------------------------------------------------
extern "C" void kernel_launch(void* const* d_in, const int* in_sizes, int n_in,
                              void* d_out, int out_size) {
    const int*   index    = (const int*)  d_in[0];
    const float* rate     = (const float*)d_in[1];
    const float* start    = (const float*)d_in[2];
    const float* endt     = (const float*)d_in[3];
    const float* t0       = (const float*)d_in[4];
    const int*   group_id = (const int*)  d_in[5];
    const float* weights  = (const float*)d_in[6];
    float* out = (float*)d_out;

    fused_kernel<<<NBLK, NTHR>>>(index, rate, start, endt, t0,
                                 group_id, weights, out);
}